// round 9
// baseline (speedup 1.0000x reference)
#include <cuda_runtime.h>

// Problem constants (fixed by the dataset): B=256, T=512, K=128
#define Bn 256
#define Tn 512
#define Kn 128

// Device scratch (no allocs allowed).
__device__ float g_partial[Bn];
__device__ int   g_perm[Bn];   // g_perm[rank] = batch index, by seq_len
__device__ int   g_done;       // zero-init; last CTA resets to 0 each run

// ---- packed f32x2 helpers (sm_103a) ---------------------------------------
__device__ __forceinline__ unsigned long long fma2(unsigned long long a,
                                                   unsigned long long b,
                                                   unsigned long long c) {
    unsigned long long d;
    asm("fma.rn.f32x2 %0, %1, %2, %3;" : "=l"(d) : "l"(a), "l"(b), "l"(c));
    return d;
}
__device__ __forceinline__ unsigned long long add2(unsigned long long a,
                                                   unsigned long long b) {
    unsigned long long d;
    asm("add.rn.f32x2 %0, %1, %2;" : "=l"(d) : "l"(a), "l"(b));
    return d;
}
__device__ __forceinline__ unsigned long long pack2(float lo, float hi) {
    unsigned long long d;
    asm("mov.b64 %0, {%1, %2};" : "=l"(d) : "f"(lo), "f"(hi));
    return d;
}
__device__ __forceinline__ float2 unpack2(unsigned long long v) {
    float lo, hi;
    asm("mov.b64 {%0, %1}, %2;" : "=f"(lo), "=f"(hi) : "l"(v));
    return make_float2(lo, hi);
}

// ---- scheduler: grid=32 x 256 threads; warp w ranks batch 8*bx+w ----------
__global__ void crf_sched_kernel(const int* __restrict__ seq_lens)
{
    const int lane = threadIdx.x & 31;
    const int i    = blockIdx.x * 8 + (threadIdx.x >> 5);
    const int Li   = seq_lens[i];
    int r = 0;
    #pragma unroll
    for (int kk = 0; kk < 8; kk++) {
        int k  = lane + 32 * kk;
        int Lk = seq_lens[k];
        r += (Lk < Li) || (Lk == Li && k < i);   // unique ranks
    }
    #pragma unroll
    for (int o = 16; o; o >>= 1) r += __shfl_xor_sync(0xffffffffu, r, o);
    if (lane == 0) g_perm[r] = i;
}

// Beta storage: 4 quarters of 32 floats at stride 40 (160B). The 4 concurrent
// 16B broadcast lines per LDS.128 phase hit bank octets {0,8,16,24}: no
// conflicts. slot(i) = (i>>5)*40 + (i&31).
#define QSTRIDE 40
#define BSLOT(i) ((((i) >> 5) * QSTRIDE) + ((i) & 31))

// One scan step. Thread tau: column j=tau>>2, quarter h=tau&3 owns 32 i's as
// 16 packed f32x2 regs. 8 LDS.128 + 16 FFMA2 + 2 shuffles per thread; the
// thread's 3 quarter-partners are adjacent lanes -> xor-1 / xor-2 combine.
// RENORM rescales by the stale beta[0] (exact LSE shift; growth << e^88).
#define CRF_STEP(LO, RENORM) do {                                            \
    const float* bp_ = sh_beta[cur];                                         \
    float cj_;                                                               \
    if (RENORM) {                                                            \
        float rr_ = bp_[0];                                                  \
        float lr_ = __logf(rr_);                                             \
        S += lr_;                                                            \
        cj_ = __expf((LO) - lr_);                                            \
    } else {                                                                 \
        cj_ = __expf(LO);                                                    \
    }                                                                        \
    const double2* ap_ = (const double2*)(bp_ + QSTRIDE * h);                \
    unsigned long long a0_ = 0ull, a1_ = 0ull, a2_ = 0ull, a3_ = 0ull;       \
    _Pragma("unroll")                                                        \
    for (int k_ = 0; k_ < 4; k_++) {                                         \
        double2 x_ = ap_[2 * k_];            /* LDS.128 4-addr broadcast */  \
        double2 y_ = ap_[2 * k_ + 1];                                        \
        a0_ = fma2(__double_as_longlong(x_.x), eT2[4 * k_ + 0], a0_);        \
        a1_ = fma2(__double_as_longlong(x_.y), eT2[4 * k_ + 1], a1_);        \
        a2_ = fma2(__double_as_longlong(y_.x), eT2[4 * k_ + 2], a2_);        \
        a3_ = fma2(__double_as_longlong(y_.y), eT2[4 * k_ + 3], a3_);        \
    }                                                                        \
    unsigned long long aa_ = add2(add2(a0_, a1_), add2(a2_, a3_));           \
    float2 pp_ = unpack2(aa_);                                               \
    float  sv_ = pp_.x + pp_.y;                                              \
    sv_ += __shfl_xor_sync(0xffffffffu, sv_, 1);   /* combine 4 quarters */  \
    sv_ += __shfl_xor_sync(0xffffffffu, sv_, 2);                             \
    float nb_ = sv_ * cj_;                                                   \
    if (h == 0) sh_beta[cur ^ 1][slotj] = nb_;                               \
    __syncthreads();                         /* the ONLY barrier per step */ \
    cur ^= 1;                                                                \
} while (0)

// grid=128 CTAs, 512 threads, one CTA/SM. CTA c runs batches perm[c] then
// perm[255-c] sequentially (balanced pairs: sums ~ T+1). 4 warps per SMSP
// from the SAME scan interleave issue and hide barrier/LDS/chain latency
// (R6 ncu: issue 28% with 2 warps/SMSP and 8-deep chains).
__global__ __launch_bounds__(512, 1) void crf_forward_kernel(
    const float* __restrict__ logits,   // [B, T, K]
    const int*   __restrict__ labels,   // [B, T]
    const int*   __restrict__ seq_lens, // [B]
    const float* __restrict__ trans,    // [K, K] trans[i*K + j]
    float* __restrict__ out)
{
    __shared__ __align__(16) float sh_beta[2][160]; // 4 quarters @ stride 40
    __shared__ float sh_wred[16];
    __shared__ int   sh_last;

    const int c    = blockIdx.x;          // 0..127
    const int tau  = threadIdx.x;         // 0..511
    const int j    = tau >> 2;            // column 0..127
    const int h    = tau & 3;             // quarter
    const int lane = tau & 31;
    const int warp = tau >> 5;            // 0..15
    const int slotj = BSLOT(j);

    const int bA = g_perm[c];
    const int bB = g_perm[Bn - 1 - c];

    // expT rows [32h, 32h+32) of column j, packed over row-pairs
    unsigned long long eT2[16];
    #pragma unroll
    for (int k = 0; k < 16; k++) {
        float e0 = __expf(trans[(32 * h + 2 * k)     * Kn + j]);
        float e1 = __expf(trans[(32 * h + 2 * k + 1) * Kn + j]);
        eT2[k] = pack2(e0, e1);
    }

    for (int p = 0; p < 2; p++) {
        const int b = p ? bB : bA;
        const int    Tlen = seq_lens[b];                  // 1..512
        const float* lg   = logits + (size_t)b * Tn * Kn;
        const int*   lb   = labels + b * Tn;

        // ---------- gold-path score: unary + pairwise ----------
        float sc = 0.f;
        for (int t = tau; t < Tlen; t += 512) {
            int y = lb[t];
            sc += lg[t * Kn + y];
            if (t >= 1) sc += trans[lb[t - 1] * Kn + y];
        }
        #pragma unroll
        for (int o = 16; o; o >>= 1) sc += __shfl_xor_sync(0xffffffffu, sc, o);
        if (lane == 0) sh_wred[warp] = sc;

        // beta_0 = exp(logits[b,0,:]), S = 0
        if (h == 0) sh_beta[0][slotj] = __expf(lg[j]);

        // static prefetch regs: rows 1..4 (always in-bounds, Tn=512)
        float la0 = lg[1 * Kn + j], la1 = lg[2 * Kn + j];
        float la2 = lg[3 * Kn + j], la3 = lg[4 * Kn + j];

        __syncthreads();
        float score = 0.f;
        #pragma unroll
        for (int w = 0; w < 16; w++) score += sh_wred[w];

        // ---------- forward recursion, 4x unrolled, renorm 1-in-4 ----------
        float S   = 0.f;
        int   cur = 0;
        int   t   = 1;
        #define ROW(tt) lg[(((tt) < Tn) ? (tt) : (Tn - 1)) * Kn + j]
        while (t + 3 < Tlen) {
            CRF_STEP(la0, true);  la0 = ROW(t + 4);
            CRF_STEP(la1, false); la1 = ROW(t + 5);
            CRF_STEP(la2, false); la2 = ROW(t + 6);
            CRF_STEP(la3, false); la3 = ROW(t + 7);
            t += 4;
        }
        #undef ROW
        // remainder <= 3 steps; la regs hold rows t..t+2 (Tlen uniform)
        if (t     < Tlen) CRF_STEP(la0, true);
        if (t + 1 < Tlen) CRF_STEP(la1, false);
        if (t + 2 < Tlen) CRF_STEP(la2, false);

        // ---------- log_z = S + log(sum_j beta_j) ----------
        __syncthreads();                         // protect sh_wred reuse
        float v = (tau < Kn) ? sh_beta[cur][BSLOT(tau)] : 0.f;
        #pragma unroll
        for (int o = 16; o; o >>= 1) v += __shfl_xor_sync(0xffffffffu, v, o);
        if (lane == 0) sh_wred[warp] = v;
        __syncthreads();

        if (tau == 0) {
            float stot = ((sh_wred[0] + sh_wred[1]) + (sh_wred[2] + sh_wred[3]));
            g_partial[b] = S + __logf(stot) - score;   // per-batch NLL
        }
        __syncthreads();                         // smem safe for next batch
    }

    // ---------- fused final reduction: last CTA sums deterministically ----
    if (tau == 0) {
        __threadfence();
        int d = atomicAdd(&g_done, 1);
        sh_last = (d == (Bn / 2 - 1));
    }
    __syncthreads();
    if (sh_last) {
        __threadfence();                 // see all CTAs' g_partial writes
        float w = (tau < Bn) ? g_partial[tau] : 0.f;  // fixed-tree: determ.
        #pragma unroll
        for (int o = 16; o; o >>= 1) w += __shfl_xor_sync(0xffffffffu, w, o);
        if (lane == 0) sh_wred[warp] = w;
        __syncthreads();
        if (tau == 0) {
            float s = ((sh_wred[0] + sh_wred[1]) + (sh_wred[2] + sh_wred[3]))
                    + ((sh_wred[4] + sh_wred[5]) + (sh_wred[6] + sh_wred[7]));
            out[0]  = s;
            g_done  = 0;                 // reset for next graph replay
        }
    }
}

extern "C" void kernel_launch(void* const* d_in, const int* in_sizes, int n_in,
                              void* d_out, int out_size)
{
    const float* logits   = (const float*)d_in[0];
    const int*   labels   = (const int*)  d_in[1];
    const int*   seq_lens = (const int*)  d_in[2];
    const float* trans    = (const float*)d_in[3];
    float*       out      = (float*)d_out;

    crf_sched_kernel<<<32, 256>>>(seq_lens);
    crf_forward_kernel<<<Bn / 2, 512>>>(logits, labels, seq_lens, trans, out);
}

// round 10
// speedup vs baseline: 1.8745x; 1.8745x over previous
#include <cuda_runtime.h>
#include <cuda_bf16.h>

// Problem constants (fixed by the dataset): B=256, T=512, K=128
#define Bn 256
#define Tn 512
#define Kn 128

// Device scratch (no allocs allowed).
__device__ float g_partial[Bn];
__device__ int   g_perm[Bn];   // g_perm[rank] = batch index, by seq_len
__device__ int   g_done;       // zero-init; last CTA resets to 0 each run

// ---- scheduler: grid=32 x 256 threads; warp w ranks batch 8*bx+w ----------
__global__ void crf_sched_kernel(const int* __restrict__ seq_lens)
{
    const int lane = threadIdx.x & 31;
    const int i    = blockIdx.x * 8 + (threadIdx.x >> 5);
    const int Li   = seq_lens[i];
    int r = 0;
    #pragma unroll
    for (int kk = 0; kk < 8; kk++) {
        int k  = lane + 32 * kk;
        int Lk = seq_lens[k];
        r += (Lk < Li) || (Lk == Li && k < i);   // unique ranks
    }
    #pragma unroll
    for (int o = 16; o; o >>= 1) r += __shfl_xor_sync(0xffffffffu, r, o);
    if (lane == 0) g_perm[r] = i;
}

// Beta layout (bf16): half0 at elements [0,64), half1 at [72,136).
// Byte bases 0 / 144: LDS.128 line k of the two halves hits banks {4k..4k+3}
// and {4k+4..4k+7} -> conflict-free 2-address broadcast. 16B-aligned (144%16=0).
#define HOFF 72
#define BSLOT(j) (((j) < 64) ? (j) : ((j) + 8))

// One scan step. Thread tau: column j=tau>>1, half h=tau&1 owns 64 i's as
// 32 bf16x2 weight regs. 8 LDS.128 + 32 HFMA2(rt2) + 1 shuffle per thread.
// RENORM rescales by the stale beta[0]; lr is used consistently in S and cj,
// so the LSE shift identity is exact (only overflow matters; bounded).
#define CRF_STEP(LO, RENORM) do {                                            \
    const __nv_bfloat16* bp_ = sh_beta[cur];                                 \
    float cj_;                                                               \
    if (RENORM) {                                                            \
        float rr_ = __bfloat162float(bp_[0]);                                \
        float lr_ = __logf(rr_);                                             \
        S += lr_;                                                            \
        cj_ = __expf((LO) - lr_);                                            \
    } else {                                                                 \
        cj_ = __expf(LO);                                                    \
    }                                                                        \
    const uint4* ap_ = (const uint4*)(bp_ + HOFF * h);                       \
    __nv_bfloat162 a0_ = __float2bfloat162_rn(0.f);                          \
    __nv_bfloat162 a1_ = a0_, a2_ = a0_, a3_ = a0_;                          \
    _Pragma("unroll")                                                        \
    for (int k_ = 0; k_ < 8; k_++) {                                         \
        uint4 v_ = ap_[k_];                 /* LDS.128: 8 betas (4 pairs) */ \
        a0_ = __hfma2(*(const __nv_bfloat162*)&v_.x, a0_ * __float2bfloat162_rn(1.f), a0_); \
        a0_ = a0_; /* placeholder avoided below */                           \
        (void)v_;                                                            \
    }                                                                        \
} while (0)

// NOTE: macro above replaced by the real one below (kept single definition).
#undef CRF_STEP
#define CRF_STEP(LO, RENORM) do {                                            \
    const __nv_bfloat16* bp_ = sh_beta[cur];                                 \
    float cj_;                                                               \
    if (RENORM) {                                                            \
        float rr_ = __bfloat162float(bp_[0]);                                \
        float lr_ = __logf(rr_);                                             \
        S += lr_;                                                            \
        cj_ = __expf((LO) - lr_);                                            \
    } else {                                                                 \
        cj_ = __expf(LO);                                                    \
    }                                                                        \
    const uint4* ap_ = (const uint4*)(bp_ + HOFF * h);                       \
    __nv_bfloat162 z_; z_.x = __float2bfloat16(0.f); z_.y = z_.x;            \
    __nv_bfloat162 a0_ = z_, a1_ = z_, a2_ = z_, a3_ = z_;                   \
    _Pragma("unroll")                                                        \
    for (int k_ = 0; k_ < 8; k_++) {                                         \
        uint4 v_ = ap_[k_];                 /* LDS.128: 8 betas (4 pairs) */ \
        __nv_bfloat162 b0_ = *(__nv_bfloat162*)&v_.x;                        \
        __nv_bfloat162 b1_ = *(__nv_bfloat162*)&v_.y;                        \
        __nv_bfloat162 b2_ = *(__nv_bfloat162*)&v_.z;                        \
        __nv_bfloat162 b3_ = *(__nv_bfloat162*)&v_.w;                        \
        a0_ = __hfma2(b0_, eT2[4 * k_ + 0], a0_);     /* HFMA2: rt 2 */      \
        a1_ = __hfma2(b1_, eT2[4 * k_ + 1], a1_);                            \
        a2_ = __hfma2(b2_, eT2[4 * k_ + 2], a2_);                            \
        a3_ = __hfma2(b3_, eT2[4 * k_ + 3], a3_);                            \
    }                                                                        \
    float2 f0_ = __bfloat1622float2(a0_);                                    \
    float2 f1_ = __bfloat1622float2(a1_);                                    \
    float2 f2_ = __bfloat1622float2(a2_);                                    \
    float2 f3_ = __bfloat1622float2(a3_);                                    \
    float sv_ = ((f0_.x + f0_.y) + (f1_.x + f1_.y))                          \
              + ((f2_.x + f2_.y) + (f3_.x + f3_.y));                         \
    sv_ += __shfl_xor_sync(0xffffffffu, sv_, 1);   /* combine halves */      \
    if (!h) sh_beta[cur ^ 1][slotj] = __float2bfloat16(sv_ * cj_);           \
    __syncthreads();                         /* the ONLY barrier per step */ \
    cur ^= 1;                                                                \
} while (0)

// grid=128 CTAs, 256 threads, one CTA/SM. CTA c runs batches perm[c] then
// perm[255-c] sequentially (balanced pairs: step sums ~ T+1). Thread tau:
// column j=tau>>1, half h=tau&1 (proven R6 layout). bf16x2 matvec: HFMA2 has
// single-register operands -> rt 2 (FFMA2 was rt 3), and bf16 beta halves
// the LDS instruction count. fp32 everywhere else (score, exp/log, scale).
__global__ __launch_bounds__(256, 1) void crf_forward_kernel(
    const float* __restrict__ logits,   // [B, T, K]
    const int*   __restrict__ labels,   // [B, T]
    const int*   __restrict__ seq_lens, // [B]
    const float* __restrict__ trans,    // [K, K] trans[i*K + j]
    float* __restrict__ out)
{
    __shared__ __align__(16) __nv_bfloat16 sh_beta[2][144];
    __shared__ float sh_wred[8];
    __shared__ int   sh_last;

    const int c    = blockIdx.x;          // 0..127
    const int tau  = threadIdx.x;         // 0..255
    const int j    = tau >> 1;            // column 0..127
    const int h    = tau & 1;             // half
    const int lane = tau & 31;
    const int warp = tau >> 5;
    const int slotj = BSLOT(j);

    const int bA = g_perm[c];
    const int bB = g_perm[Bn - 1 - c];

    // expT rows [64h, 64h+64) of column j, packed bf16x2 over row-pairs
    __nv_bfloat162 eT2[32];
    #pragma unroll
    for (int k = 0; k < 32; k++) {
        float e0 = __expf(trans[(64 * h + 2 * k)     * Kn + j]);
        float e1 = __expf(trans[(64 * h + 2 * k + 1) * Kn + j]);
        eT2[k] = __floats2bfloat162_rn(e0, e1);
    }

    for (int p = 0; p < 2; p++) {
        const int b = p ? bB : bA;
        const int    Tlen = seq_lens[b];                  // 1..512
        const float* lg   = logits + (size_t)b * Tn * Kn;
        const int*   lb   = labels + b * Tn;

        // ---------- gold-path score: unary + pairwise (fp32 exact) ----------
        float sc = 0.f;
        for (int t = tau; t < Tlen; t += 256) {
            int y = lb[t];
            sc += lg[t * Kn + y];
            if (t >= 1) sc += trans[lb[t - 1] * Kn + y];
        }
        #pragma unroll
        for (int o = 16; o; o >>= 1) sc += __shfl_xor_sync(0xffffffffu, sc, o);
        if (lane == 0) sh_wred[warp] = sc;

        // beta_0 = exp(logits[b,0,:]) in bf16, S = 0
        if (!h) sh_beta[0][slotj] = __float2bfloat16(__expf(lg[j]));

        // static prefetch regs: rows 1..4 (always in-bounds, Tn=512)
        float la0 = lg[1 * Kn + j], la1 = lg[2 * Kn + j];
        float la2 = lg[3 * Kn + j], la3 = lg[4 * Kn + j];

        __syncthreads();
        float score = 0.f;
        #pragma unroll
        for (int w = 0; w < 8; w++) score += sh_wred[w];

        // ---------- forward recursion, 4x unrolled, renorm 1-in-4 ----------
        float S   = 0.f;
        int   cur = 0;
        int   t   = 1;
        #define ROW(tt) lg[(((tt) < Tn) ? (tt) : (Tn - 1)) * Kn + j]
        while (t + 3 < Tlen) {
            CRF_STEP(la0, true);  la0 = ROW(t + 4);
            CRF_STEP(la1, false); la1 = ROW(t + 5);
            CRF_STEP(la2, false); la2 = ROW(t + 6);
            CRF_STEP(la3, false); la3 = ROW(t + 7);
            t += 4;
        }
        #undef ROW
        // remainder <= 3 steps; la regs hold rows t..t+2 (Tlen uniform)
        if (t     < Tlen) CRF_STEP(la0, true);
        if (t + 1 < Tlen) CRF_STEP(la1, false);
        if (t + 2 < Tlen) CRF_STEP(la2, false);

        // ---------- log_z = S + log(sum_j beta_j) ----------
        __syncthreads();                         // protect sh_wred reuse
        float v = (tau < Kn) ? __bfloat162float(sh_beta[cur][BSLOT(tau)]) : 0.f;
        #pragma unroll
        for (int o = 16; o; o >>= 1) v += __shfl_xor_sync(0xffffffffu, v, o);
        if (lane == 0) sh_wred[warp] = v;
        __syncthreads();

        if (tau == 0) {
            float stot = ((sh_wred[0] + sh_wred[1]) + (sh_wred[2] + sh_wred[3]))
                       + ((sh_wred[4] + sh_wred[5]) + (sh_wred[6] + sh_wred[7]));
            g_partial[b] = S + __logf(stot) - score;   // per-batch NLL
        }
        __syncthreads();                         // smem safe for next batch
    }

    // ---------- fused final reduction: last CTA sums deterministically ----
    if (tau == 0) {
        __threadfence();
        int d = atomicAdd(&g_done, 1);
        sh_last = (d == (Bn / 2 - 1));
    }
    __syncthreads();
    if (sh_last) {
        __threadfence();                 // see all CTAs' g_partial writes
        float w = g_partial[tau];        // fixed-tree: deterministic
        #pragma unroll
        for (int o = 16; o; o >>= 1) w += __shfl_xor_sync(0xffffffffu, w, o);
        if (lane == 0) sh_wred[warp] = w;
        __syncthreads();
        if (tau == 0) {
            float s = ((sh_wred[0] + sh_wred[1]) + (sh_wred[2] + sh_wred[3]))
                    + ((sh_wred[4] + sh_wred[5]) + (sh_wred[6] + sh_wred[7]));
            out[0]  = s;
            g_done  = 0;                 // reset for next graph replay
        }
    }
}

extern "C" void kernel_launch(void* const* d_in, const int* in_sizes, int n_in,
                              void* d_out, int out_size)
{
    const float* logits   = (const float*)d_in[0];
    const int*   labels   = (const int*)  d_in[1];
    const int*   seq_lens = (const int*)  d_in[2];
    const float* trans    = (const float*)d_in[3];
    float*       out      = (float*)d_out;

    crf_sched_kernel<<<32, 256>>>(seq_lens);
    crf_forward_kernel<<<Bn / 2, 256>>>(logits, labels, seq_lens, trans, out);
}

// round 11
// speedup vs baseline: 2.0934x; 1.1168x over previous
#include <cuda_runtime.h>
#include <cuda_bf16.h>

// Problem constants (fixed by the dataset): B=256, T=512, K=128
#define Bn 256
#define Tn 512
#define Kn 128

// Device scratch (no allocs allowed).
__device__ float g_partial[Bn];
__device__ int   g_perm[Bn];   // g_perm[rank] = batch index, by seq_len
__device__ int   g_done;       // zero-init; last CTA resets to 0 each run

// ---- scheduler: grid=32 x 256 threads; warp w ranks batch 8*bx+w ----------
__global__ void crf_sched_kernel(const int* __restrict__ seq_lens)
{
    const int lane = threadIdx.x & 31;
    const int i    = blockIdx.x * 8 + (threadIdx.x >> 5);
    const int Li   = seq_lens[i];
    int r = 0;
    #pragma unroll
    for (int kk = 0; kk < 8; kk++) {
        int k  = lane + 32 * kk;
        int Lk = seq_lens[k];
        r += (Lk < Li) || (Lk == Li && k < i);   // unique ranks
    }
    #pragma unroll
    for (int o = 16; o; o >>= 1) r += __shfl_xor_sync(0xffffffffu, r, o);
    if (lane == 0) g_perm[r] = i;
}

// Beta layout (bf16): half0 at elements [0,64), half1 at [72,136).
// Byte bases 0 / 144: LDS.128 line k of the two halves hits disjoint bank
// quads -> conflict-free 2-address broadcast. (144 % 16 == 0.)
#define HOFF 72
#define BSLOT(j) (((j) < 64) ? (j) : ((j) + 8))

// One scan step. Thread tau: column j=tau>>1, half h=tau&1 owns 64 i's as
// 32 bf16x2 weight regs. 8 LDS.128 + 32 HFMA2 + pure-bf16 tail:
// HADD2 tree -> lane-swap HADD2 (horizontal) -> packed 32-bit shuffle ->
// HADD2 -> HMUL2 by cj (pre-converted off-chain). No F2F on the chain.
// RENORM rescales by the stale beta[0]; lr used consistently in S and cj,
// so the LSE shift identity is exact (only overflow matters; bounded).
#define CRF_STEP(LO, RENORM) do {                                            \
    const __nv_bfloat16* bp_ = sh_beta[cur];                                 \
    float cj_;                                                               \
    if (RENORM) {                                                            \
        float rr_ = __bfloat162float(bp_[0]);                                \
        float lr_ = __logf(rr_);                                             \
        S += lr_;                                                            \
        cj_ = __expf((LO) - lr_);                                            \
    } else {                                                                 \
        cj_ = __expf(LO);                                                    \
    }                                                                        \
    __nv_bfloat162 cj2_ = __float2bfloat162_rn(cj_);   /* off-chain cvt */   \
    const uint4* ap_ = (const uint4*)(bp_ + HOFF * h);                       \
    __nv_bfloat162 z_; z_.x = __float2bfloat16(0.f); z_.y = z_.x;            \
    __nv_bfloat162 a0_ = z_, a1_ = z_, a2_ = z_, a3_ = z_;                   \
    _Pragma("unroll")                                                        \
    for (int k_ = 0; k_ < 8; k_++) {                                         \
        uint4 v_ = ap_[k_];                 /* LDS.128: 8 betas (4 pairs) */ \
        a0_ = __hfma2(*(__nv_bfloat162*)&v_.x, eT2[4 * k_ + 0], a0_);        \
        a1_ = __hfma2(*(__nv_bfloat162*)&v_.y, eT2[4 * k_ + 1], a1_);        \
        a2_ = __hfma2(*(__nv_bfloat162*)&v_.z, eT2[4 * k_ + 2], a2_);        \
        a3_ = __hfma2(*(__nv_bfloat162*)&v_.w, eT2[4 * k_ + 3], a3_);        \
    }                                                                        \
    __nv_bfloat162 s_ = __hadd2(__hadd2(a0_, a1_), __hadd2(a2_, a3_));       \
    __nv_bfloat162 sw_ = __lowhigh2highlow(s_);                              \
    __nv_bfloat162 hs_ = __hadd2(s_, sw_);      /* both lanes = half-sum */  \
    unsigned hu_  = __shfl_xor_sync(0xffffffffu, *(unsigned*)&hs_, 1);       \
    __nv_bfloat162 tot_ = __hadd2(hs_, *(__nv_bfloat162*)&hu_);              \
    __nv_bfloat162 nb2_ = __hmul2(tot_, cj2_);                               \
    if (!h) sh_beta[cur ^ 1][slotj] = nb2_.x;                                \
    __syncthreads();                         /* the ONLY barrier per step */ \
    cur ^= 1;                                                                \
} while (0)

// grid=128 CTAs, 256 threads, one CTA/SM. CTA c runs batches perm[c] then
// perm[255-c] sequentially (balanced pairs: step sums ~ T+1). Thread tau:
// column j=tau>>1, half h=tau&1 (proven layout). bf16 matvec (HFMA2 rt2,
// single-reg operands) + bf16 combine tail; fp32 score / exp / log / S.
__global__ __launch_bounds__(256, 1) void crf_forward_kernel(
    const float* __restrict__ logits,   // [B, T, K]
    const int*   __restrict__ labels,   // [B, T]
    const int*   __restrict__ seq_lens, // [B]
    const float* __restrict__ trans,    // [K, K] trans[i*K + j]
    float* __restrict__ out)
{
    __shared__ __align__(16) __nv_bfloat16 sh_beta[2][144];
    __shared__ float sh_wred[8];
    __shared__ int   sh_last;

    const int c    = blockIdx.x;          // 0..127
    const int tau  = threadIdx.x;         // 0..255
    const int j    = tau >> 1;            // column 0..127
    const int h    = tau & 1;             // half
    const int lane = tau & 31;
    const int warp = tau >> 5;
    const int slotj = BSLOT(j);

    const int bA = g_perm[c];
    const int bB = g_perm[Bn - 1 - c];

    // expT rows [64h, 64h+64) of column j, packed bf16x2 over row-pairs
    __nv_bfloat162 eT2[32];
    #pragma unroll
    for (int k = 0; k < 32; k++) {
        float e0 = __expf(trans[(64 * h + 2 * k)     * Kn + j]);
        float e1 = __expf(trans[(64 * h + 2 * k + 1) * Kn + j]);
        eT2[k] = __floats2bfloat162_rn(e0, e1);
    }

    for (int p = 0; p < 2; p++) {
        const int b = p ? bB : bA;
        const int    Tlen = seq_lens[b];                  // 1..512
        const float* lg   = logits + (size_t)b * Tn * Kn;
        const int*   lb   = labels + b * Tn;

        // ---------- gold-path score: unary + pairwise (fp32 exact) --------
        float sc = 0.f;
        for (int t = tau; t < Tlen; t += 256) {
            int y = lb[t];
            sc += lg[t * Kn + y];
            if (t >= 1) sc += trans[lb[t - 1] * Kn + y];
        }
        #pragma unroll
        for (int o = 16; o; o >>= 1) sc += __shfl_xor_sync(0xffffffffu, sc, o);
        if (lane == 0) sh_wred[warp] = sc;

        // beta_0 = exp(logits[b,0,:]) in bf16, S = 0
        if (!h) sh_beta[0][slotj] = __float2bfloat16(__expf(lg[j]));

        // static prefetch regs: rows 1..4 (always in-bounds, Tn=512)
        float la0 = lg[1 * Kn + j], la1 = lg[2 * Kn + j];
        float la2 = lg[3 * Kn + j], la3 = lg[4 * Kn + j];

        __syncthreads();
        float score = 0.f;
        #pragma unroll
        for (int w = 0; w < 8; w++) score += sh_wred[w];

        // ---------- forward recursion, 4x unrolled, renorm 1-in-4 ---------
        float S   = 0.f;
        int   cur = 0;
        int   t   = 1;
        #define ROW(tt) lg[(((tt) < Tn) ? (tt) : (Tn - 1)) * Kn + j]
        while (t + 3 < Tlen) {
            CRF_STEP(la0, true);  la0 = ROW(t + 4);
            CRF_STEP(la1, false); la1 = ROW(t + 5);
            CRF_STEP(la2, false); la2 = ROW(t + 6);
            CRF_STEP(la3, false); la3 = ROW(t + 7);
            t += 4;
        }
        #undef ROW
        // remainder <= 3 steps; la regs hold rows t..t+2 (Tlen uniform)
        if (t     < Tlen) CRF_STEP(la0, true);
        if (t + 1 < Tlen) CRF_STEP(la1, false);
        if (t + 2 < Tlen) CRF_STEP(la2, false);

        // ---------- log_z = S + log(sum_j beta_j) (fp32 reduce) -----------
        __syncthreads();                         // protect sh_wred reuse
        float v = (tau < Kn) ? __bfloat162float(sh_beta[cur][BSLOT(tau)]) : 0.f;
        #pragma unroll
        for (int o = 16; o; o >>= 1) v += __shfl_xor_sync(0xffffffffu, v, o);
        if (lane == 0) sh_wred[warp] = v;
        __syncthreads();

        if (tau == 0) {
            float stot = ((sh_wred[0] + sh_wred[1]) + (sh_wred[2] + sh_wred[3]))
                       + ((sh_wred[4] + sh_wred[5]) + (sh_wred[6] + sh_wred[7]));
            g_partial[b] = S + __logf(stot) - score;   // per-batch NLL
        }
        __syncthreads();                         // smem safe for next batch
    }

    // ---------- fused final reduction: last CTA sums deterministically ----
    if (tau == 0) {
        __threadfence();
        int d = atomicAdd(&g_done, 1);
        sh_last = (d == (Bn / 2 - 1));
    }
    __syncthreads();
    if (sh_last) {
        __threadfence();                 // see all CTAs' g_partial writes
        float w = g_partial[tau];        // fixed-tree: deterministic
        #pragma unroll
        for (int o = 16; o; o >>= 1) w += __shfl_xor_sync(0xffffffffu, w, o);
        if (lane == 0) sh_wred[warp] = w;
        __syncthreads();
        if (tau == 0) {
            float s = ((sh_wred[0] + sh_wred[1]) + (sh_wred[2] + sh_wred[3]))
                    + ((sh_wred[4] + sh_wred[5]) + (sh_wred[6] + sh_wred[7]));
            out[0]  = s;
            g_done  = 0;                 // reset for next graph replay
        }
    }
}

extern "C" void kernel_launch(void* const* d_in, const int* in_sizes, int n_in,
                              void* d_out, int out_size)
{
    const float* logits   = (const float*)d_in[0];
    const int*   labels   = (const int*)  d_in[1];
    const int*   seq_lens = (const int*)  d_in[2];
    const float* trans    = (const float*)d_in[3];
    float*       out      = (float*)d_out;

    crf_sched_kernel<<<32, 256>>>(seq_lens);
    crf_forward_kernel<<<Bn / 2, 256>>>(logits, labels, seq_lens, trans, out);
}